// round 6
// baseline (speedup 1.0000x reference)
#include <cuda_runtime.h>
#include <cuda_bf16.h>

#define NELEM   16384
#define THREADS 256
#define IPT     4
#define TI      (THREADS * IPT)      // 1024 i per block
#define TJ      256                  // j tile staged in shared
#define JCHUNK  512                  // j span per block
#define GRIDX   (NELEM / TI)         // 16
#define GRIDY   (NELEM / JCHUNK)     // 32
#define NBLOCKS (GRIDX * GRIDY)      // 512
#define RED_T   512

// Device globals (zero-initialized at module load; rebuilt every launch).
__device__ float g_bsum[NBLOCKS];
__device__ int   g_hist[NELEM];
__device__ int   g_cum[NELEM];    // inclusive prefix of hist
__device__ int   g_off[NELEM];    // scatter cursors (exclusive base, consumed)
__device__ float g_ssort[NELEM];  // scores permuted into rank-sorted order
__device__ int   g_start[NELEM];  // suffix start (cum[rank]) per sorted position

__global__ void zero_hist_kernel() {
    g_hist[blockIdx.x * blockDim.x + threadIdx.x] = 0;
}

__global__ void hist_kernel(const int* __restrict__ ranks) {
    const int i = blockIdx.x * blockDim.x + threadIdx.x;
    atomicAdd(&g_hist[ranks[i] & (NELEM - 1)], 1);  // int atomics: deterministic
}

// Inclusive prefix scan of g_hist (16384 bins) in one block.
__global__ __launch_bounds__(512)
void scan_kernel() {
    __shared__ int tot[512];
    const int tid = threadIdx.x;
    int loc[32];
    int run = 0;
#pragma unroll
    for (int k = 0; k < 32; ++k) {
        run += g_hist[tid * 32 + k];
        loc[k] = run;
    }
    tot[tid] = run;
    __syncthreads();
#pragma unroll
    for (int off = 1; off < 512; off <<= 1) {   // Hillis–Steele inclusive scan
        const int v   = tot[tid];
        const int add = (tid >= off) ? tot[tid - off] : 0;
        __syncthreads();
        tot[tid] = v + add;
        __syncthreads();
    }
    const int base = (tid > 0) ? tot[tid - 1] : 0;
#pragma unroll
    for (int k = 0; k < 32; ++k) {
        const int r = tid * 32 + k;
        g_cum[r] = base + loc[k];                        // inclusive
        g_off[r] = base + (k > 0 ? loc[k - 1] : 0);      // exclusive (cursor)
    }
}

// Counting-sort scatter: scores into rank-sorted order. Intra-tie order is
// atomic-dependent but tie groups align with suffix boundaries, so the
// result is permutation-invariant (float order noise ~1e-7 << 1e-3).
__global__ void scatter_kernel(const float* __restrict__ scores,
                               const int* __restrict__ ranks) {
    const int i = blockIdx.x * blockDim.x + threadIdx.x;
    const int r = ranks[i] & (NELEM - 1);
    const int slot = atomicAdd(&g_off[r], 1);
    g_ssort[slot] = scores[i];
    g_start[slot] = g_cum[r];   // first position with strictly greater rank
}

// Triangular pair kernel over rank-sorted positions:
// pair (p, q) contributes max(1 - s_p + s_q, 0) iff q >= start_p.
__global__ __launch_bounds__(THREADS)
void pair_kernel() {
    __shared__ float tile[TJ];
    __shared__ float red_s[THREADS / 32];

    const int tid   = threadIdx.x;
    const int ibase = blockIdx.x * TI;
    const int jbase = blockIdx.y * JCHUNK;
    const int bid   = blockIdx.y * GRIDX + blockIdx.x;

    // Block-level skip: start is monotone in sorted position, so the block
    // minimum is g_start[ibase]. Uniform branch; no barriers crossed.
    if (jbase + JCHUNK <= g_start[ibase]) {
        if (tid == 0) g_bsum[bid] = 0.0f;
        return;
    }

    float cst[IPT];
    int   st[IPT];
#pragma unroll
    for (int k = 0; k < IPT; ++k) {
        const int p = ibase + tid + k * THREADS;
        cst[k] = 1.0f - g_ssort[p];
        st[k]  = g_start[p];        // monotone: st[0] <= ... <= st[IPT-1]
    }

    float acc[IPT] = {0.0f, 0.0f, 0.0f, 0.0f};

    for (int jt = 0; jt < JCHUNK; jt += TJ) {
        tile[tid] = g_ssort[jbase + jt + tid];
        __syncthreads();

        const int jb = jbase + jt;
        if (jb >= st[IPT - 1]) {
            // Whole tile inside every k's suffix: compare-free 3-inst loop.
#pragma unroll 8
            for (int jj = 0; jj < TJ; ++jj) {
                const float sj = tile[jj];
#pragma unroll
                for (int k = 0; k < IPT; ++k)
                    acc[k] += fmaxf(cst[k] + sj, 0.0f);
            }
        } else if (jb + TJ > st[0]) {
            // Diagonal band: per-pair position compare.
#pragma unroll 4
            for (int jj = 0; jj < TJ; ++jj) {
                const float sj  = tile[jj];
                const int   pos = jb + jj;
#pragma unroll
                for (int k = 0; k < IPT; ++k) {
                    const bool  p = pos >= st[k];
                    const float t = fmaxf(cst[k] + sj, 0.0f);
                    acc[k] += p ? t : 0.0f;
                }
            }
        }
        // else: tile entirely below all suffixes — contributes nothing.
        __syncthreads();
    }

    float lsum = (acc[0] + acc[1]) + (acc[2] + acc[3]);
#pragma unroll
    for (int off = 16; off; off >>= 1)
        lsum += __shfl_down_sync(0xffffffffu, lsum, off);
    if ((tid & 31) == 0) red_s[tid >> 5] = lsum;
    __syncthreads();
    if (tid == 0) {
        float bs = 0.0f;
#pragma unroll
        for (int w = 0; w < THREADS / 32; ++w) bs += red_s[w];
        g_bsum[bid] = bs;
    }
}

__global__ __launch_bounds__(RED_T)
void final_reduce_kernel(float* __restrict__ out) {
    __shared__ double    ws[RED_T / 32];
    __shared__ long long wc[RED_T / 32];
    const int tid  = threadIdx.x;
    const int lane = tid & 31;
    const int warp = tid >> 5;

    double s = (double)g_bsum[tid];          // NBLOCKS == RED_T
    long long c2 = 0;
#pragma unroll
    for (int k = 0; k < NELEM / RED_T; ++k) {
        const long long c = (long long)g_hist[tid * (NELEM / RED_T) + k];
        c2 += c * c;
    }
#pragma unroll
    for (int off = 16; off; off >>= 1) {
        s  += __shfl_down_sync(0xffffffffu, s, off);
        c2 += __shfl_down_sync(0xffffffffu, c2, off);
    }
    if (lane == 0) { ws[warp] = s; wc[warp] = c2; }
    __syncthreads();
    if (warp == 0) {
        s  = (lane < RED_T / 32) ? ws[lane] : 0.0;
        c2 = (lane < RED_T / 32) ? wc[lane] : 0LL;
#pragma unroll
        for (int off = 8; off; off >>= 1) {
            s  += __shfl_down_sync(0xffffffffu, s, off);
            c2 += __shfl_down_sync(0xffffffffu, c2, off);
        }
        if (lane == 0) {
            const long long total = (long long)NELEM * (long long)NELEM;
            const long long cnt   = (total - c2) / 2;   // ordered pairs r_i < r_j
            out[0] = (cnt > 0) ? (float)(s / (double)cnt) : 0.0f;
        }
    }
}

extern "C" void kernel_launch(void* const* d_in, const int* in_sizes, int n_in,
                              void* d_out, int out_size) {
    const float* scores = (const float*)d_in[0];
    const int*   ranks  = (const int*)d_in[1];
    float*       out    = (float*)d_out;

    zero_hist_kernel<<<NELEM / 256, 256>>>();
    hist_kernel<<<NELEM / 256, 256>>>(ranks);
    scan_kernel<<<1, 512>>>();
    scatter_kernel<<<NELEM / 256, 256>>>(scores, ranks);
    pair_kernel<<<dim3(GRIDX, GRIDY), THREADS>>>();
    final_reduce_kernel<<<1, RED_T>>>(out);
}

// round 10
// speedup vs baseline: 1.8163x; 1.8163x over previous
#include <cuda_runtime.h>
#include <cuda_bf16.h>

#define NELEM   16384
#define THREADS 256
#define IPT     8                    // i's per thread (register blocked)
#define TI      (THREADS * IPT)      // 2048 i per block
#define TJ      256                  // j tile per block (single shared tile)
#define GRIDX   (NELEM / TI)         // 8
#define GRIDY   (NELEM / TJ)         // 64
#define NBLOCKS (GRIDX * GRIDY)      // 512
#define RED_T   512

__device__ float g_bsum[NBLOCKS];
__device__ int   g_hist[NELEM];

__global__ void zero_hist_kernel() {
    g_hist[blockIdx.x * blockDim.x + threadIdx.x] = 0;
}

__global__ void hist_kernel(const int* __restrict__ ranks) {
    const int i = blockIdx.x * blockDim.x + threadIdx.x;
    // ranks in [0, NELEM); mask converts any surprise into a wrong answer
    // (detectable) instead of a fault. Integer atomics: order-independent.
    atomicAdd(&g_hist[ranks[i] & (NELEM - 1)], 1);
}

__global__ __launch_bounds__(THREADS)
void pair_tile_kernel(const float* __restrict__ scores,
                      const int* __restrict__ ranks) {
    __shared__ float2 tile[TJ];
    __shared__ float  red_s[THREADS / 32];

    const int tid   = threadIdx.x;
    const int ibase = blockIdx.x * TI;
    const int jbase = blockIdx.y * TJ;

    // Hoist per-i state: c = 1 - s_i, plus this i's rank.
    float cst[IPT];
    int   ri[IPT];
#pragma unroll
    for (int k = 0; k < IPT; ++k) {
        const int i = ibase + tid + k * THREADS;
        cst[k] = 1.0f - scores[i];
        ri[k]  = ranks[i];
    }

    {
        const int j = jbase + tid;
        tile[tid] = make_float2(scores[j], __int_as_float(ranks[j]));
    }
    __syncthreads();

    // 8 independent accumulator chains: 1 dependent FADD per chain per jj,
    // so the 4-cyc FADD RAW latency never binds (issue/pipe-bound instead).
    float acc[IPT];
#pragma unroll
    for (int k = 0; k < IPT; ++k) acc[k] = 0.0f;

#pragma unroll 4
    for (int jj = 0; jj < TJ; ++jj) {
        const float2 v  = tile[jj];            // warp-uniform broadcast LDS.64
        const float  sj = v.x;
        const int    rj = __float_as_int(v.y);
#pragma unroll
        for (int k = 0; k < IPT; ++k) {
            const bool  p = ri[k] < rj;
            const float t = fmaxf(cst[k] + sj, 0.0f);
            acc[k] += p ? t : 0.0f;
        }
    }

    float lsum = ((acc[0] + acc[1]) + (acc[2] + acc[3]))
               + ((acc[4] + acc[5]) + (acc[6] + acc[7]));

    // Warp reduce, then cross-warp via shared.
#pragma unroll
    for (int off = 16; off; off >>= 1)
        lsum += __shfl_down_sync(0xffffffffu, lsum, off);
    if ((tid & 31) == 0) red_s[tid >> 5] = lsum;
    __syncthreads();
    if (tid == 0) {
        float bs = 0.0f;
#pragma unroll
        for (int w = 0; w < THREADS / 32; ++w) bs += red_s[w];
        g_bsum[blockIdx.y * GRIDX + blockIdx.x] = bs;
    }
}

__global__ __launch_bounds__(RED_T)
void final_reduce_kernel(float* __restrict__ out) {
    __shared__ double    ws[RED_T / 32];
    __shared__ long long wc[RED_T / 32];
    const int tid  = threadIdx.x;
    const int lane = tid & 31;
    const int warp = tid >> 5;

    double s = (double)g_bsum[tid];          // NBLOCKS == RED_T
    long long c2 = 0;
#pragma unroll
    for (int k = 0; k < NELEM / RED_T; ++k) {
        const long long c = (long long)g_hist[tid * (NELEM / RED_T) + k];
        c2 += c * c;
    }
#pragma unroll
    for (int off = 16; off; off >>= 1) {
        s  += __shfl_down_sync(0xffffffffu, s, off);
        c2 += __shfl_down_sync(0xffffffffu, c2, off);
    }
    if (lane == 0) { ws[warp] = s; wc[warp] = c2; }
    __syncthreads();
    if (warp == 0) {
        s  = (lane < RED_T / 32) ? ws[lane] : 0.0;
        c2 = (lane < RED_T / 32) ? wc[lane] : 0LL;
#pragma unroll
        for (int off = 8; off; off >>= 1) {
            s  += __shfl_down_sync(0xffffffffu, s, off);
            c2 += __shfl_down_sync(0xffffffffu, c2, off);
        }
        if (lane == 0) {
            const long long total = (long long)NELEM * (long long)NELEM;
            const long long cnt   = (total - c2) / 2;   // ordered pairs r_i < r_j
            out[0] = (cnt > 0) ? (float)(s / (double)cnt) : 0.0f;
        }
    }
}

extern "C" void kernel_launch(void* const* d_in, const int* in_sizes, int n_in,
                              void* d_out, int out_size) {
    const float* scores = (const float*)d_in[0];
    const int*   ranks  = (const int*)d_in[1];
    float*       out    = (float*)d_out;

    zero_hist_kernel<<<NELEM / 256, 256>>>();
    hist_kernel<<<NELEM / 256, 256>>>(ranks);
    pair_tile_kernel<<<dim3(GRIDX, GRIDY), THREADS>>>(scores, ranks);
    final_reduce_kernel<<<1, RED_T>>>(out);
}

// round 14
// speedup vs baseline: 2.3484x; 1.2930x over previous
#include <cuda_runtime.h>
#include <cuda_bf16.h>

#define NELEM   16384
#define THREADS 256
#define IPT     4
#define TI      (THREADS * IPT)      // 1024 i-rows per block
#define TJ      256                  // 256 j-cols per block (one shared tile)
#define NTI     (NELEM / TI)         // 16 i-tile columns
#define NTJ     (NELEM / TJ)         // 64 j-tiles
// Upper-triangular tile count: sum_{it} (64 - 4*it) = 544
#define NBLOCKS 544
#define SCAN_T  512

// Device globals (zero-init at load; rebuilt deterministically every launch).
__device__ float     g_bsum[NBLOCKS];
__device__ int       g_hist[NELEM];   // scan kernel re-zeroes after consuming
__device__ int       g_cum[NELEM];    // inclusive prefix (suffix start per rank)
__device__ int       g_off[NELEM];    // scatter cursors (exclusive prefix)
__device__ float     g_ssort[NELEM];  // scores in rank-sorted order
__device__ int       g_start[NELEM];  // cum[rank] per sorted position (monotone)
__device__ long long g_c2;            // sum of squared rank multiplicities

__global__ void hist_kernel(const int* __restrict__ ranks) {
    const int i = blockIdx.x * blockDim.x + threadIdx.x;
    // ranks in [0, NELEM); mask turns surprises into wrong answers, not faults.
    atomicAdd(&g_hist[ranks[i] & (NELEM - 1)], 1);
}

// One block: inclusive scan of 16384 bins via 32 coalesced tiles of 512,
// computes sum(c^2), and resets g_hist to zero for the next replay.
__global__ __launch_bounds__(SCAN_T)
void scan_kernel() {
    __shared__ int wsum[SCAN_T / 32];
    const int tid  = threadIdx.x;
    const int lane = tid & 31;
    const int wid  = tid >> 5;

    int carry = 0;
    long long c2 = 0;

    for (int t = 0; t < NELEM / SCAN_T; ++t) {
        const int b = t * SCAN_T + tid;            // lane-consecutive: coalesced
        const int v = g_hist[b];
        c2 += (long long)v * (long long)v;

        // Warp-inclusive scan.
        int x = v;
#pragma unroll
        for (int o = 1; o < 32; o <<= 1) {
            const int n = __shfl_up_sync(0xffffffffu, x, o);
            if (lane >= o) x += n;
        }
        if (lane == 31) wsum[wid] = x;
        __syncthreads();
        if (wid == 0 && lane < SCAN_T / 32) {
            int y = wsum[lane];
#pragma unroll
            for (int o = 1; o < SCAN_T / 32; o <<= 1) {
                const int n = __shfl_up_sync(0xffffu, y, o);
                if (lane >= o) y += n;
            }
            wsum[lane] = y;
        }
        __syncthreads();

        const int incl = x + (wid > 0 ? wsum[wid - 1] : 0) + carry;
        g_cum[b]  = incl;          // coalesced
        g_off[b]  = incl - v;      // coalesced
        g_hist[b] = 0;             // reset for next launch (coalesced)
        carry += wsum[(SCAN_T / 32) - 1];
        __syncthreads();           // protect wsum reuse next tile
    }

    // Block-reduce c2 -> g_c2.
    __shared__ long long wc[SCAN_T / 32];
#pragma unroll
    for (int o = 16; o; o >>= 1) c2 += __shfl_down_sync(0xffffffffu, c2, o);
    if (lane == 0) wc[wid] = c2;
    __syncthreads();
    if (wid == 0) {
        long long s = (lane < SCAN_T / 32) ? wc[lane] : 0LL;
#pragma unroll
        for (int o = 8; o; o >>= 1) s += __shfl_down_sync(0xffffffffu, s, o);
        if (lane == 0) g_c2 = s;
    }
}

// Counting-sort scatter. Intra-tie order is atomic-dependent, but tie groups
// align exactly with suffix boundaries, so the final sum is invariant up to
// fp reordering (~1e-7, far below 1e-3).
__global__ void scatter_kernel(const float* __restrict__ scores,
                               const int* __restrict__ ranks) {
    const int i = blockIdx.x * blockDim.x + threadIdx.x;
    const int r = ranks[i] & (NELEM - 1);
    const int slot = atomicAdd(&g_off[r], 1);
    g_ssort[slot] = scores[i];
    g_start[slot] = g_cum[r];   // first position with strictly greater rank
}

// Triangular pair kernel over rank-sorted positions:
// pair (p, q) contributes max(1 - s_p + s_q, 0) iff q >= g_start[p].
// Grid enumerates ONLY upper-triangular tiles (jt >= 4*it); unlaunched tiles
// satisfy q < ibase <= p < g_start[p], contributing 0.
__global__ __launch_bounds__(THREADS)
void pair_kernel() {
    __shared__ float tile[TJ];
    __shared__ float red_s[THREADS / 32];

    const int tid = threadIdx.x;
    const int bid = blockIdx.x;

    // bid -> (it, jt): C(it) = 66*it - 2*it*it tiles precede column it.
    int it = 0;
#pragma unroll
    for (int c = 1; c < NTI; ++c) {
        if (bid >= 66 * c - 2 * c * c) it = c;
    }
    const int jt    = 4 * it + (bid - (66 * it - 2 * it * it));
    const int ibase = it * TI;
    const int jb    = jt * TJ;

    // Block-uniform classification (g_start monotone in sorted position).
    const int st_min = g_start[ibase];
    const int st_max = g_start[ibase + TI - 1];

    if (jb + TJ <= st_min) {            // uniform skip (rare: only via ties)
        if (tid == 0) g_bsum[bid] = 0.0f;
        return;
    }

    float cst[IPT];
    int   st[IPT];
#pragma unroll
    for (int k = 0; k < IPT; ++k) {
        const int p = ibase + tid + k * THREADS;
        cst[k] = 1.0f - g_ssort[p];
        st[k]  = g_start[p];
    }
    tile[tid] = g_ssort[jb + tid];
    __syncthreads();

    float acc[IPT] = {0.0f, 0.0f, 0.0f, 0.0f};

    if (jb >= st_max) {
        // Entire tile inside every p's suffix: compare-free, 3 inst/pair.
#pragma unroll 8
        for (int jj = 0; jj < TJ; ++jj) {
            const float sj = tile[jj];
#pragma unroll
            for (int k = 0; k < IPT; ++k)
                acc[k] += fmaxf(cst[k] + sj, 0.0f);
        }
    } else {
        // Diagonal band: general path with per-pair position compare.
#pragma unroll 4
        for (int jj = 0; jj < TJ; ++jj) {
            const float sj  = tile[jj];
            const int   pos = jb + jj;
#pragma unroll
            for (int k = 0; k < IPT; ++k) {
                const bool  p = pos >= st[k];
                const float t = fmaxf(cst[k] + sj, 0.0f);
                acc[k] += p ? t : 0.0f;
            }
        }
    }

    float lsum = (acc[0] + acc[1]) + (acc[2] + acc[3]);
#pragma unroll
    for (int off = 16; off; off >>= 1)
        lsum += __shfl_down_sync(0xffffffffu, lsum, off);
    if ((tid & 31) == 0) red_s[tid >> 5] = lsum;
    __syncthreads();
    if (tid == 0) {
        float bs = 0.0f;
#pragma unroll
        for (int w = 0; w < THREADS / 32; ++w) bs += red_s[w];
        g_bsum[bid] = bs;
    }
}

__global__ __launch_bounds__(256)
void final_reduce_kernel(float* __restrict__ out) {
    __shared__ double ws[8];
    const int tid  = threadIdx.x;
    const int lane = tid & 31;
    const int wid  = tid >> 5;

    double s = 0.0;
    for (int b = tid; b < NBLOCKS; b += 256)   // lane-consecutive: coalesced
        s += (double)g_bsum[b];
#pragma unroll
    for (int o = 16; o; o >>= 1) s += __shfl_down_sync(0xffffffffu, s, o);
    if (lane == 0) ws[wid] = s;
    __syncthreads();
    if (wid == 0) {
        s = (lane < 8) ? ws[lane] : 0.0;
#pragma unroll
        for (int o = 4; o; o >>= 1) s += __shfl_down_sync(0xffffffffu, s, o);
        if (lane == 0) {
            const long long total = (long long)NELEM * (long long)NELEM;
            const long long cnt   = (total - g_c2) / 2;  // ordered pairs r_i<r_j
            out[0] = (cnt > 0) ? (float)(s / (double)cnt) : 0.0f;
        }
    }
}

extern "C" void kernel_launch(void* const* d_in, const int* in_sizes, int n_in,
                              void* d_out, int out_size) {
    const float* scores = (const float*)d_in[0];
    const int*   ranks  = (const int*)d_in[1];
    float*       out    = (float*)d_out;

    hist_kernel<<<NELEM / 256, 256>>>(ranks);
    scan_kernel<<<1, SCAN_T>>>();
    scatter_kernel<<<NELEM / 256, 256>>>(scores, ranks);
    pair_kernel<<<NBLOCKS, THREADS>>>();
    final_reduce_kernel<<<1, 256>>>(out);
}